// round 4
// baseline (speedup 1.0000x reference)
#include <cuda_runtime.h>
#include <cstdint>

// MixtureLowRankRNN — GB300 sm_103a.
// Subspace identity: h_t ∈ colspan([m|I]) (h0=0), so outputs are basis coords:
//   y[:,t,0:4]  = a_s*S_{t+1},  S <- 0.9 S + u_t,  u_t = n^T tanh(h_t)
//   y[:,t,4:20] = 0.1*X_{t+1},  X <- 0.9 X + x_t
// tanh fold: u_r = NS_r - 2*R_r, R_r = sum_h n[h,r]*sig_h, sig = 1/(1+e^{2h}).
// This round: 2 independent batches interleaved per CTA (shared weights) to
// fill the ~800 stall cycles/step observed in the single-batch version.

#define RANKN 4
#define INPN  16
#define TLEN  1024
#define BATCH 32
#define NTHR  256
#define BPC   2     // batches per CTA

typedef unsigned long long u64;

__device__ __forceinline__ u64 pack2(float x, float y) {
    u64 r; asm("mov.b64 %0, {%1, %2};" : "=l"(r) : "f"(x), "f"(y)); return r;
}
__device__ __forceinline__ void unpack2(u64 v, float& x, float& y) {
    asm("mov.b64 {%0, %1}, %2;" : "=f"(x), "=f"(y) : "l"(v));
}
__device__ __forceinline__ u64 fma2(u64 a, u64 b, u64 c) {
    u64 d; asm("fma.rn.f32x2 %0, %1, %2, %3;" : "=l"(d) : "l"(a), "l"(b), "l"(c)); return d;
}
__device__ __forceinline__ u64 mul2(u64 a, u64 b) {
    u64 d; asm("mul.rn.f32x2 %0, %1, %2;" : "=l"(d) : "l"(a), "l"(b)); return d;
}
__device__ __forceinline__ u64 add2(u64 a, u64 b) {
    u64 d; asm("add.rn.f32x2 %0, %1, %2;" : "=l"(d) : "l"(a), "l"(b)); return d;
}

// sig(x) = 1/(1 + e^{2x}) = (1 - tanh x)/2, accurate to ~1e-6.
__device__ __forceinline__ float rcore(float x) {
    float e, r;
    asm("ex2.approx.f32 %0, %1;" : "=f"(e) : "f"(x * 2.885390081777927f)); // 2*log2(e)
    asm("rcp.approx.f32 %0, %1;" : "=f"(r) : "f"(e + 1.0f));
    return r;
}

// 6-shfl transposed warp reduce: returns warp-sum of p_{lane&3}.
__device__ __forceinline__ float warp_reduce4(float p0, float p1, float p2, float p3, int lane) {
    const bool b0 = lane & 1;
    const bool b1 = lane & 2;
    float sA = b0 ? p0 : p1;
    float rA = __shfl_xor_sync(0xffffffffu, sA, 1);
    float q0 = (b0 ? p1 : p0) + rA;
    float sB = b0 ? p2 : p3;
    float rB = __shfl_xor_sync(0xffffffffu, sB, 1);
    float q1 = (b0 ? p3 : p2) + rB;
    float sC = b1 ? q0 : q1;
    float rC = __shfl_xor_sync(0xffffffffu, sC, 2);
    float w  = (b1 ? q1 : q0) + rC;
    w += __shfl_xor_sync(0xffffffffu, w, 4);
    w += __shfl_xor_sync(0xffffffffu, w, 8);
    w += __shfl_xor_sync(0xffffffffu, w, 16);
    return w;
}

__global__ __launch_bounds__(NTHR, 1)
void rnn_kernel(const float* __restrict__ x,   // [B, T, 16]
                const float* __restrict__ m,   // [H, 4]
                const float* __restrict__ n,   // [H, 4]
                const float* __restrict__ I,   // [H, 16]
                float* __restrict__ out)       // [B, T, 20]
{
    const int cb   = blockIdx.x;        // 0..15, handles batches 2cb, 2cb+1
    const int tid  = threadIdx.x;
    const int wid  = tid >> 5;
    const int lane = tid & 31;

    __shared__ float4 s_part[2][BPC][8];     // [buf][batch][warp] partial R0..R3
    __shared__ u64    s_x2[4][BPC][INPN];    // duplicated x_t pairs, 4-deep rotate

    const float a_s = 0.1f * (500.0f / 1024.0f);
    const int eA0 = tid,        eA1 = tid + 256;
    const int eB0 = tid + 512,  eB1 = tid + 768;

    u64 na[RANKN], nb[RANKN], msA[RANKN], msB[RANKN];
    u64 m2a[RANKN], m2b[RANKN], Ia[INPN], Ib[INPN];
#pragma unroll
    for (int r = 0; r < RANKN; r++) {
        na[r]  = pack2(n[eA0 * RANKN + r], n[eA1 * RANKN + r]);
        nb[r]  = pack2(n[eB0 * RANKN + r], n[eB1 * RANKN + r]);
        msA[r] = pack2(a_s * m[eA0 * RANKN + r], a_s * m[eA1 * RANKN + r]);
        msB[r] = pack2(a_s * m[eB0 * RANKN + r], a_s * m[eB1 * RANKN + r]);
    }
#pragma unroll
    for (int j = 0; j < INPN; j++) {
        Ia[j] = pack2(0.1f * I[eA0 * INPN + j], 0.1f * I[eA1 * INPN + j]);
        Ib[j] = pack2(0.1f * I[eB0 * INPN + j], 0.1f * I[eB1 * INPN + j]);
    }

    const u64 c9   = pack2(0.9f, 0.9f);
    const u64 neg2 = pack2(-2.0f, -2.0f);
    const u64 asd  = pack2(a_s, a_s);

    const float* xb[BPC];
    float*       outb[BPC];
#pragma unroll
    for (int q = 0; q < BPC; q++) {
        xb[q]   = x   + (size_t)(cb * BPC + q) * TLEN * INPN;
        outb[q] = out + (size_t)(cb * BPC + q) * TLEN * 20;
    }

    // role state (each role lives in a distinct warp; scalars are private)
    u64   S01 = 0ull, S23 = 0ull;             // warp0 (batch0), warp4 (batch1)
    float X = 0.f, xv = 0.f, xn = 0.f, xf = 0.f;  // warp1 (b0), warp2 (b1)

    // ================= prologue: NS_r = sum_h n[h,r], stage x_0 =============
    {
        float p[4];
#pragma unroll
        for (int r = 0; r < RANKN; r++) {
            float lo, hi; unpack2(add2(na[r], nb[r]), lo, hi);
            p[r] = lo + hi;
        }
        float w = warp_reduce4(p[0], p[1], p[2], p[3], lane);
        if (lane < 4) ((float*)&s_part[1][0][wid])[lane] = w;
#pragma unroll
        for (int q = 0; q < BPC; q++) {
            if (wid == 1 + q && lane < INPN) {
                xv = xb[q][lane];
                xn = xb[q][INPN + lane];
                s_x2[0][q][lane] = pack2(xv, xv);
            }
        }
    }
    __syncthreads();

    u64 NS01, NS23;
    {
        const float4* sp = s_part[1][0];
        ulonglong2 v[8];
#pragma unroll
        for (int i = 0; i < 8; i++) v[i] = *(const ulonglong2*)&sp[i];
        NS01 = add2(add2(add2(v[0].x, v[1].x), add2(v[2].x, v[3].x)),
                    add2(add2(v[4].x, v[5].x), add2(v[6].x, v[7].x)));
        NS23 = add2(add2(add2(v[0].y, v[1].y), add2(v[2].y, v[3].y)),
                    add2(add2(v[4].y, v[5].y), add2(v[6].y, v[7].y)));
    }
    float ns0, ns1, ns2, ns3;
    unpack2(NS01, ns0, ns1); unpack2(NS23, ns2, ns3);
    const u64 N0d = pack2(ns0, ns0), N1d = pack2(ns1, ns1);
    const u64 N2d = pack2(ns2, ns2), N3d = pack2(ns3, ns3);

    // kA = sum_r (a_s*m_r)*NS_r ; m2 = -2 * (a_s*m)
    const u64 kAa = fma2(msA[0], N0d, fma2(msA[1], N1d, fma2(msA[2], N2d, mul2(msA[3], N3d))));
    const u64 kAb = fma2(msB[0], N0d, fma2(msB[1], N1d, fma2(msB[2], N2d, mul2(msB[3], N3d))));
#pragma unroll
    for (int r = 0; r < RANKN; r++) {
        m2a[r] = mul2(msA[r], neg2);
        m2b[r] = mul2(msB[r], neg2);
    }

    u64 hA[BPC], hB[BPC];
#pragma unroll
    for (int q = 0; q < BPC; q++) { hA[q] = 0ull; hB[q] = 0ull; }

    // ================= main recurrence =================
    for (int t = 0; t < TLEN; t++) {
        // ---- per batch: sig(h), low-rank dot, warp reduce, publish ----
#pragma unroll
        for (int q = 0; q < BPC; q++) {
            float a0, a1, b0v, b1v;
            unpack2(hA[q], a0, a1); unpack2(hB[q], b0v, b1v);
            u64 rA = pack2(rcore(a0), rcore(a1));
            u64 rB = pack2(rcore(b0v), rcore(b1v));
            float p[4];
#pragma unroll
            for (int r = 0; r < RANKN; r++) {
                float lo, hi; unpack2(fma2(na[r], rA, mul2(nb[r], rB)), lo, hi);
                p[r] = lo + hi;
            }
            float w = warp_reduce4(p[0], p[1], p[2], p[3], lane);
            if (lane < 4) ((float*)&s_part[t & 1][q][wid])[lane] = w;
        }

        // ---- per batch: u-independent update, 4 parallel chains ----
        u64 accA[BPC], accB[BPC];
#pragma unroll
        for (int q = 0; q < BPC; q++) {
            const ulonglong2* xp = (const ulonglong2*)s_x2[t & 3][q];
            ulonglong2 xq0 = xp[0], xq1 = xp[1], xq2 = xp[2], xq3 = xp[3];
            u64 aA0 = fma2(c9, hA[q], kAa);
            u64 aB0 = fma2(c9, hB[q], kAb);
            u64 aA1 = fma2(Ia[2], xq1.x, mul2(Ia[0], xq0.x));
            u64 aB1 = fma2(Ib[2], xq1.x, mul2(Ib[0], xq0.x));
            u64 aA2 = fma2(Ia[4], xq2.x, mul2(Ia[1], xq0.y));
            u64 aB2 = fma2(Ib[4], xq2.x, mul2(Ib[1], xq0.y));
            u64 aA3 = fma2(Ia[5], xq2.y, mul2(Ia[3], xq1.y));
            u64 aB3 = fma2(Ib[5], xq2.y, mul2(Ib[3], xq1.y));
            ulonglong2 xq4 = xp[4], xq5 = xp[5], xq6 = xp[6], xq7 = xp[7];
            aA0 = fma2(Ia[6],  xq3.x, aA0);  aB0 = fma2(Ib[6],  xq3.x, aB0);
            aA1 = fma2(Ia[7],  xq3.y, aA1);  aB1 = fma2(Ib[7],  xq3.y, aB1);
            aA2 = fma2(Ia[8],  xq4.x, aA2);  aB2 = fma2(Ib[8],  xq4.x, aB2);
            aA3 = fma2(Ia[9],  xq4.y, aA3);  aB3 = fma2(Ib[9],  xq4.y, aB3);
            aA0 = fma2(Ia[10], xq5.x, aA0);  aB0 = fma2(Ib[10], xq5.x, aB0);
            aA1 = fma2(Ia[11], xq5.y, aA1);  aB1 = fma2(Ib[11], xq5.y, aB1);
            aA2 = fma2(Ia[12], xq6.x, aA2);  aB2 = fma2(Ib[12], xq6.x, aB2);
            aA3 = fma2(Ia[13], xq6.y, aA3);  aB3 = fma2(Ib[13], xq6.y, aB3);
            aA0 = fma2(Ia[14], xq7.x, aA0);  aB0 = fma2(Ib[14], xq7.x, aB0);
            aA1 = fma2(Ia[15], xq7.y, aA1);  aB1 = fma2(Ib[15], xq7.y, aB1);
            accA[q] = add2(add2(aA0, aA1), add2(aA2, aA3));
            accB[q] = add2(add2(aB0, aB1), add2(aB2, aB3));
        }

        // ---- stage x_{t+1}, prefetch x_{t+2} (warp1: b0, warp2: b1) ----
#pragma unroll
        for (int q = 0; q < BPC; q++) {
            if (wid == 1 + q && lane < INPN) {
                s_x2[(t + 1) & 3][q][lane] = pack2(xn, xn);
                xf = (t + 2 < TLEN) ? xb[q][(size_t)(t + 2) * INPN + lane] : 0.f;
            }
        }

        __syncthreads();   // the only barrier per step (serves both batches)

        // ---- per batch: cross-warp combine, correction, outputs ----
#pragma unroll
        for (int q = 0; q < BPC; q++) {
            const float4* sp = s_part[t & 1][q];
            ulonglong2 v[8];
#pragma unroll
            for (int i = 0; i < 8; i++) v[i] = *(const ulonglong2*)&sp[i];
            u64 R01 = add2(add2(add2(v[0].x, v[1].x), add2(v[2].x, v[3].x)),
                           add2(add2(v[4].x, v[5].x), add2(v[6].x, v[7].x)));
            u64 R23 = add2(add2(add2(v[0].y, v[1].y), add2(v[2].y, v[3].y)),
                           add2(add2(v[4].y, v[5].y), add2(v[6].y, v[7].y)));

            float c0, c1, c2, c3;
            unpack2(R01, c0, c1); unpack2(R23, c2, c3);
            u64 R0d = pack2(c0, c0), R1d = pack2(c1, c1);
            u64 R2d = pack2(c2, c2), R3d = pack2(c3, c3);

            u64 cA0 = fma2(m2a[1], R1d, mul2(m2a[0], R0d));
            u64 cB0 = fma2(m2b[1], R1d, mul2(m2b[0], R0d));
            u64 cA1 = fma2(m2a[3], R3d, mul2(m2a[2], R2d));
            u64 cB1 = fma2(m2b[3], R3d, mul2(m2b[2], R2d));
            hA[q] = add2(accA[q], add2(cA0, cA1));
            hB[q] = add2(accB[q], add2(cB0, cB1));

            // low-rank coordinate output (warp0 for b0, warp4 for b1)
            if (wid == (q ? 4 : 0) && lane == 0) {
                u64 u01 = fma2(neg2, R01, NS01);   // u = NS - 2R
                u64 u23 = fma2(neg2, R23, NS23);
                S01 = fma2(c9, S01, u01);
                S23 = fma2(c9, S23, u23);
                float o0, o1, o2, o3;
                unpack2(mul2(asd, S01), o0, o1);
                unpack2(mul2(asd, S23), o2, o3);
                *(float4*)(outb[q] + (size_t)t * 20) = make_float4(o0, o1, o2, o3);
            }
            // input coordinate output + x register rotate
            if (wid == 1 + q && lane < INPN) {
                X = fmaf(0.9f, X, xv);
                outb[q][(size_t)t * 20 + 4 + lane] = 0.1f * X;
                xv = xn;
                xn = xf;
            }
        }
    }
}

extern "C" void kernel_launch(void* const* d_in, const int* in_sizes, int n_in,
                              void* d_out, int out_size) {
    const float* x = (const float*)d_in[0];
    const float* m = (const float*)d_in[1];
    const float* n = (const float*)d_in[2];
    const float* I = (const float*)d_in[3];
    rnn_kernel<<<BATCH / BPC, NTHR>>>(x, m, n, I, (float*)d_out);
}

// round 5
// speedup vs baseline: 2.0820x; 2.0820x over previous
#include <cuda_runtime.h>
#include <cstdint>

// MixtureLowRankRNN — GB300 sm_103a.
// Subspace identity: h_t ∈ colspan([m|I]) (h0=0) ⇒ outputs are basis coords:
//   y[:,t,0:4]  = a_s*S_{t+1},  S <- 0.9 S + u_t,  u_t = n^T tanh(h_t)
//   y[:,t,4:20] = 0.1*X_{t+1},  X <- 0.9 X + x_t
// Round 5: back to 1 batch/CTA (2-batch regressed). tanh.approx.f32 replaces
// the ex2/rcp sigmoid fold (shorter chain). x_t comes straight from global
// via broadcast LDG.128 with 1-step register prefetch — no smem staging.

#define RANKN 4
#define INPN  16
#define TLEN  1024
#define BATCH 32
#define NTHR  256

typedef unsigned long long u64;

__device__ __forceinline__ u64 pack2(float x, float y) {
    u64 r; asm("mov.b64 %0, {%1, %2};" : "=l"(r) : "f"(x), "f"(y)); return r;
}
__device__ __forceinline__ void unpack2(u64 v, float& x, float& y) {
    asm("mov.b64 {%0, %1}, %2;" : "=f"(x), "=f"(y) : "l"(v));
}
__device__ __forceinline__ u64 fma2(u64 a, u64 b, u64 c) {
    u64 d; asm("fma.rn.f32x2 %0, %1, %2, %3;" : "=l"(d) : "l"(a), "l"(b), "l"(c)); return d;
}
__device__ __forceinline__ u64 mul2(u64 a, u64 b) {
    u64 d; asm("mul.rn.f32x2 %0, %1, %2;" : "=l"(d) : "l"(a), "l"(b)); return d;
}
__device__ __forceinline__ u64 add2(u64 a, u64 b) {
    u64 d; asm("add.rn.f32x2 %0, %1, %2;" : "=l"(d) : "l"(a), "l"(b)); return d;
}
__device__ __forceinline__ float tanha(float x) {
    float r; asm("tanh.approx.f32 %0, %1;" : "=f"(r) : "f"(x)); return r;
}

// 6-shfl transposed warp reduce: returns warp-sum of p_{lane&3}.
__device__ __forceinline__ float warp_reduce4(float p0, float p1, float p2, float p3, int lane) {
    const bool b0 = lane & 1;
    const bool b1 = lane & 2;
    float sA = b0 ? p0 : p1;
    float rA = __shfl_xor_sync(0xffffffffu, sA, 1);
    float q0 = (b0 ? p1 : p0) + rA;
    float sB = b0 ? p2 : p3;
    float rB = __shfl_xor_sync(0xffffffffu, sB, 1);
    float q1 = (b0 ? p3 : p2) + rB;
    float sC = b1 ? q0 : q1;
    float rC = __shfl_xor_sync(0xffffffffu, sC, 2);
    float w  = (b1 ? q1 : q0) + rC;
    w += __shfl_xor_sync(0xffffffffu, w, 4);
    w += __shfl_xor_sync(0xffffffffu, w, 8);
    w += __shfl_xor_sync(0xffffffffu, w, 16);
    return w;
}

__global__ __launch_bounds__(NTHR, 1)
void rnn_kernel(const float* __restrict__ x,   // [B, T, 16]
                const float* __restrict__ m,   // [H, 4]
                const float* __restrict__ n,   // [H, 4]
                const float* __restrict__ I,   // [H, 16]
                float* __restrict__ out)       // [B, T, 20]
{
    const int b    = blockIdx.x;
    const int tid  = threadIdx.x;
    const int wid  = tid >> 5;
    const int lane = tid & 31;

    __shared__ float4 s_part[2][8];   // [buf][warp] partial {u0..u3}

    const float a_s = 0.1f * (500.0f / 1024.0f);
    const int eA0 = tid,        eA1 = tid + 256;
    const int eB0 = tid + 512,  eB1 = tid + 768;

    u64 na[RANKN], nb[RANKN], mcA[RANKN], mcB[RANKN], Ia[INPN], Ib[INPN];
#pragma unroll
    for (int r = 0; r < RANKN; r++) {
        na[r]  = pack2(n[eA0 * RANKN + r], n[eA1 * RANKN + r]);
        nb[r]  = pack2(n[eB0 * RANKN + r], n[eB1 * RANKN + r]);
        mcA[r] = pack2(a_s * m[eA0 * RANKN + r], a_s * m[eA1 * RANKN + r]);
        mcB[r] = pack2(a_s * m[eB0 * RANKN + r], a_s * m[eB1 * RANKN + r]);
    }
#pragma unroll
    for (int j = 0; j < INPN; j++) {
        Ia[j] = pack2(0.1f * I[eA0 * INPN + j], 0.1f * I[eA1 * INPN + j]);
        Ib[j] = pack2(0.1f * I[eB0 * INPN + j], 0.1f * I[eB1 * INPN + j]);
    }

    const u64 c9  = pack2(0.9f, 0.9f);
    const u64 asd = pack2(a_s, a_s);

    const float* xb   = x   + (size_t)b * TLEN * INPN;
    float*       outb = out + (size_t)b * TLEN * 20;

    // current x_t duplicated into f32x2 pairs (registers, no smem)
    u64 xd[INPN];
    {
        const float4* xr = (const float4*)xb;
        float4 f0 = xr[0], f1 = xr[1], f2 = xr[2], f3 = xr[3];
        xd[0]=pack2(f0.x,f0.x); xd[1]=pack2(f0.y,f0.y); xd[2]=pack2(f0.z,f0.z); xd[3]=pack2(f0.w,f0.w);
        xd[4]=pack2(f1.x,f1.x); xd[5]=pack2(f1.y,f1.y); xd[6]=pack2(f1.z,f1.z); xd[7]=pack2(f1.w,f1.w);
        xd[8]=pack2(f2.x,f2.x); xd[9]=pack2(f2.y,f2.y); xd[10]=pack2(f2.z,f2.z); xd[11]=pack2(f2.w,f2.w);
        xd[12]=pack2(f3.x,f3.x); xd[13]=pack2(f3.y,f3.y); xd[14]=pack2(f3.z,f3.z); xd[15]=pack2(f3.w,f3.w);
    }

    u64 hA = 0ull, hB = 0ull;
    u64 S01 = 0ull, S23 = 0ull;      // warp0 lane0
    float X = 0.f, xv = 0.f;         // warp1 lanes 0..15
    if (wid == 1 && lane < INPN) xv = xb[lane];

    for (int t = 0; t < TLEN; t++) {
        // ---- prefetch x_{t+1} (broadcast LDG, latency spans the step) ----
        const size_t tn = (t + 1 < TLEN) ? (size_t)(t + 1) : (size_t)t;
        const float4* xrn = (const float4*)(xb + tn * INPN);
        float4 nf0 = xrn[0], nf1 = xrn[1], nf2 = xrn[2], nf3 = xrn[3];
        float xvn = 0.f;
        if (wid == 1 && lane < INPN) xvn = xb[tn * INPN + lane];

        // ---- critical path: tanh(h), low-rank dot, warp reduce ----
        float a0, a1, b0v, b1v;
        unpack2(hA, a0, a1); unpack2(hB, b0v, b1v);
        u64 thA = pack2(tanha(a0), tanha(a1));
        u64 thB = pack2(tanha(b0v), tanha(b1v));

        float p[4];
#pragma unroll
        for (int r = 0; r < RANKN; r++) {
            float lo, hi; unpack2(fma2(na[r], thA, mul2(nb[r], thB)), lo, hi);
            p[r] = lo + hi;
        }
        float w = warp_reduce4(p[0], p[1], p[2], p[3], lane);
        if (lane < 4) ((float*)&s_part[t & 1][wid])[lane] = w;

        // ---- u-independent update: 4 parallel fma2 chains ----
        u64 aA0 = mul2(c9, hA);
        u64 aB0 = mul2(c9, hB);
        u64 aA1 = fma2(Ia[1], xd[1], mul2(Ia[0], xd[0]));
        u64 aB1 = fma2(Ib[1], xd[1], mul2(Ib[0], xd[0]));
        u64 aA2 = fma2(Ia[3], xd[3], mul2(Ia[2], xd[2]));
        u64 aB2 = fma2(Ib[3], xd[3], mul2(Ib[2], xd[2]));
        u64 aA3 = fma2(Ia[5], xd[5], mul2(Ia[4], xd[4]));
        u64 aB3 = fma2(Ib[5], xd[5], mul2(Ib[4], xd[4]));
        aA0 = fma2(Ia[6],  xd[6],  aA0);  aB0 = fma2(Ib[6],  xd[6],  aB0);
        aA1 = fma2(Ia[7],  xd[7],  aA1);  aB1 = fma2(Ib[7],  xd[7],  aB1);
        aA2 = fma2(Ia[8],  xd[8],  aA2);  aB2 = fma2(Ib[8],  xd[8],  aB2);
        aA3 = fma2(Ia[9],  xd[9],  aA3);  aB3 = fma2(Ib[9],  xd[9],  aB3);
        aA0 = fma2(Ia[10], xd[10], aA0);  aB0 = fma2(Ib[10], xd[10], aB0);
        aA1 = fma2(Ia[11], xd[11], aA1);  aB1 = fma2(Ib[11], xd[11], aB1);
        aA2 = fma2(Ia[12], xd[12], aA2);  aB2 = fma2(Ib[12], xd[12], aB2);
        aA3 = fma2(Ia[13], xd[13], aA3);  aB3 = fma2(Ib[13], xd[13], aB3);
        aA0 = fma2(Ia[14], xd[14], aA0);  aB0 = fma2(Ib[14], xd[14], aB0);
        aA1 = fma2(Ia[15], xd[15], aA1);  aB1 = fma2(Ib[15], xd[15], aB1);
        u64 accA = add2(add2(aA0, aA1), add2(aA2, aA3));
        u64 accB = add2(add2(aB0, aB1), add2(aB2, aB3));

        __syncthreads();   // the only barrier per step

        // ---- cross-warp combine (broadcast LDS.128 + f32x2 tree) ----
        const float4* sp = s_part[t & 1];
        ulonglong2 v0 = *(const ulonglong2*)&sp[0];
        ulonglong2 v1 = *(const ulonglong2*)&sp[1];
        ulonglong2 v2 = *(const ulonglong2*)&sp[2];
        ulonglong2 v3 = *(const ulonglong2*)&sp[3];
        ulonglong2 v4 = *(const ulonglong2*)&sp[4];
        ulonglong2 v5 = *(const ulonglong2*)&sp[5];
        ulonglong2 v6 = *(const ulonglong2*)&sp[6];
        ulonglong2 v7 = *(const ulonglong2*)&sp[7];
        u64 U01 = add2(add2(add2(v0.x, v1.x), add2(v2.x, v3.x)),
                       add2(add2(v4.x, v5.x), add2(v6.x, v7.x)));
        u64 U23 = add2(add2(add2(v0.y, v1.y), add2(v2.y, v3.y)),
                       add2(add2(v4.y, v5.y), add2(v6.y, v7.y)));

        float q0, q1, q2, q3;
        unpack2(U01, q0, q1); unpack2(U23, q2, q3);
        u64 U0d = pack2(q0, q0), U1d = pack2(q1, q1);
        u64 U2d = pack2(q2, q2), U3d = pack2(q3, q3);

        // h_{t+1} = acc + sum_r (a_s m_r) u_r
        u64 cA0 = fma2(mcA[1], U1d, mul2(mcA[0], U0d));
        u64 cB0 = fma2(mcB[1], U1d, mul2(mcB[0], U0d));
        u64 cA1 = fma2(mcA[3], U3d, mul2(mcA[2], U2d));
        u64 cB1 = fma2(mcB[3], U3d, mul2(mcB[2], U2d));
        hA = add2(accA, add2(cA0, cA1));
        hB = add2(accB, add2(cB0, cB1));

        // ---- outputs (role warps, off critical path) ----
        if (wid == 0 && lane == 0) {
            S01 = fma2(c9, S01, U01);
            S23 = fma2(c9, S23, U23);
            float o0, o1, o2, o3;
            unpack2(mul2(asd, S01), o0, o1);
            unpack2(mul2(asd, S23), o2, o3);
            *(float4*)(outb + (size_t)t * 20) = make_float4(o0, o1, o2, o3);
        } else if (wid == 1 && lane < INPN) {
            X = fmaf(0.9f, X, xv);
            outb[(size_t)t * 20 + 4 + lane] = 0.1f * X;
            xv = xvn;
        }

        // ---- rotate prefetched x into duplicated pairs ----
        xd[0]=pack2(nf0.x,nf0.x); xd[1]=pack2(nf0.y,nf0.y); xd[2]=pack2(nf0.z,nf0.z); xd[3]=pack2(nf0.w,nf0.w);
        xd[4]=pack2(nf1.x,nf1.x); xd[5]=pack2(nf1.y,nf1.y); xd[6]=pack2(nf1.z,nf1.z); xd[7]=pack2(nf1.w,nf1.w);
        xd[8]=pack2(nf2.x,nf2.x); xd[9]=pack2(nf2.y,nf2.y); xd[10]=pack2(nf2.z,nf2.z); xd[11]=pack2(nf2.w,nf2.w);
        xd[12]=pack2(nf3.x,nf3.x); xd[13]=pack2(nf3.y,nf3.y); xd[14]=pack2(nf3.z,nf3.z); xd[15]=pack2(nf3.w,nf3.w);
    }
}

extern "C" void kernel_launch(void* const* d_in, const int* in_sizes, int n_in,
                              void* d_out, int out_size) {
    const float* x = (const float*)d_in[0];
    const float* m = (const float*)d_in[1];
    const float* n = (const float*)d_in[2];
    const float* I = (const float*)d_in[3];
    rnn_kernel<<<BATCH, NTHR>>>(x, m, n, I, (float*)d_out);
}